// round 14
// baseline (speedup 1.0000x reference)
#include <cuda_runtime.h>
#include <cuda_fp16.h>
#include <cstdint>
#include <stdint.h>

#define Bn 8
#define Tn 4096
#define Cn 128
#define HSn 64
#define BQ 128

// scale = 1/sqrt(C) folded with log2(e) so we can use ex2.approx
#define QSCALE (0.08838834764831845f * 1.4426950408889634f)

// Scratch (device globals — no allocation allowed in kernel_launch)
__device__ __align__(16) __half g_Q[Bn * Tn * HSn];
__device__ __align__(16) __half g_K[Bn * Tn * HSn];
__device__ __align__(16) __half g_V[Bn * Tn * HSn];
__device__ __align__(16) __half g_po[2 * Bn * Tn * HSn];  // NORMALIZED O partials (fp16)
__device__ float g_pm[2 * Bn * Tn];
__device__ float g_pl[2 * Bn * Tn];
__device__ int g_len[Bn];

__device__ __forceinline__ float exp2_approx(float x) {
    float y;
    asm("ex2.approx.ftz.f32 %0, %1;" : "=f"(y) : "f"(x));
    return y;
}

__device__ __forceinline__ unsigned exp2_h2(unsigned x) {
    unsigned y;
    asm("ex2.approx.f16x2 %0, %1;" : "=r"(y) : "r"(x));
    return y;
}

__device__ __forceinline__ unsigned smem_u32(const void* p) {
    return (unsigned)__cvta_generic_to_shared(p);
}

// fp32-accum HMMA (qkv kernel)
__device__ __forceinline__ void mma16816(float* c, const unsigned* a,
                                         unsigned b0, unsigned b1) {
    asm volatile(
        "mma.sync.aligned.m16n8k16.row.col.f32.f16.f16.f32 "
        "{%0,%1,%2,%3}, {%4,%5,%6,%7}, {%8,%9}, {%0,%1,%2,%3};\n"
        : "+f"(c[0]), "+f"(c[1]), "+f"(c[2]), "+f"(c[3])
        : "r"(a[0]), "r"(a[1]), "r"(a[2]), "r"(a[3]), "r"(b0), "r"(b1));
}

// fp16-accum HMMA (flash kernel) — C fragment == A fragment layout
__device__ __forceinline__ void mma16816h(unsigned* c, const unsigned* a,
                                          unsigned b0, unsigned b1) {
    asm volatile(
        "mma.sync.aligned.m16n8k16.row.col.f16.f16.f16.f16 "
        "{%0,%1}, {%2,%3,%4,%5}, {%6,%7}, {%0,%1};\n"
        : "+r"(c[0]), "+r"(c[1])
        : "r"(a[0]), "r"(a[1]), "r"(a[2]), "r"(a[3]), "r"(b0), "r"(b1));
}

__device__ __forceinline__ void ldsm4(unsigned* r, unsigned addr) {
    asm volatile("ldmatrix.sync.aligned.m8n8.x4.shared.b16 {%0,%1,%2,%3}, [%4];"
                 : "=r"(r[0]), "=r"(r[1]), "=r"(r[2]), "=r"(r[3]) : "r"(addr));
}

__device__ __forceinline__ void ldsm4t(unsigned* r, unsigned addr) {
    asm volatile("ldmatrix.sync.aligned.m8n8.x4.trans.shared.b16 {%0,%1,%2,%3}, [%4];"
                 : "=r"(r[0]), "=r"(r[1]), "=r"(r[2]), "=r"(r[3]) : "r"(addr));
}

__device__ __forceinline__ void cp_async16(unsigned dst, const void* src) {
    asm volatile("cp.async.cg.shared.global [%0], [%1], 16;\n"
                 :: "r"(dst), "l"(src));
}
__device__ __forceinline__ void cp_commit() {
    asm volatile("cp.async.commit_group;\n");
}
template <int N>
__device__ __forceinline__ void cp_wait() {
    asm volatile("cp.async.wait_group %0;\n" :: "n"(N));
}

// ---------------------------------------------------------------------------
// Kernel 1: fused QKV projection + RoPE via HMMA (fp32 accum for accuracy).
// Blocks 0..Bn-1 ALSO reduce the padding mask for their batch (replaces the
// former standalone len_kernel launch).
// ---------------------------------------------------------------------------
__global__ __launch_bounds__(384) void qkv_kernel(
    const float* __restrict__ x,
    const float* __restrict__ Wq,
    const float* __restrict__ Wk,
    const float* __restrict__ Wv,
    const float* __restrict__ fcos,
    const float* __restrict__ fsin,
    const int* __restrict__ mask)
{
    __shared__ __half Ws[3 * 128 * 64];     // 48KB: [mat][k=128][n=64], swizzled
    __shared__ int lred[12];
    int tid = threadIdx.x;

    #pragma unroll
    for (int i = 0; i < 8; i++) {
        int cid = tid + i * 384;
        int mat = cid >> 10;
        int within = cid & 1023;
        int row = within >> 3, c = within & 7;
        const float* src = (mat == 0 ? Wq : (mat == 1 ? Wk : Wv)) + row * 64 + c * 8;
        float4 f0 = *(const float4*)src;
        float4 f1 = *(const float4*)(src + 4);
        union { __half2 h[4]; uint4 u; } pk;
        pk.h[0] = __floats2half2_rn(f0.x, f0.y);
        pk.h[1] = __floats2half2_rn(f0.z, f0.w);
        pk.h[2] = __floats2half2_rn(f1.x, f1.y);
        pk.h[3] = __floats2half2_rn(f1.z, f1.w);
        int dst = mat * 8192 + row * 64 + ((c ^ (row & 7)) * 8);
        *(uint4*)(Ws + dst) = pk.u;
    }
    __syncthreads();

    int w = tid >> 5, lane = tid & 31;
    int g = lane >> 2, tq = lane & 3;
    int mat = w >> 2, rg = w & 3;
    long rowa = (long)blockIdx.x * 64 + rg * 16 + g;

    float acc[8][4];
    #pragma unroll
    for (int n = 0; n < 8; n++) { acc[n][0] = acc[n][1] = acc[n][2] = acc[n][3] = 0.f; }

    unsigned wsb = smem_u32(Ws) + (unsigned)mat * 16384u;
    int grp = lane >> 3, r8 = lane & 7;
    unsigned wrow = (unsigned)(8 * (grp & 1) + r8) * 128u;
    unsigned wsw[4];
    #pragma unroll
    for (int pv = 0; pv < 4; pv++)
        wsw[pv] = (unsigned)(((2 * pv + (grp >> 1)) ^ r8) * 16);

    const float* xa = x + rowa * Cn;
    const float* xb = xa + 8 * Cn;

    #pragma unroll
    for (int ks = 0; ks < 8; ks++) {
        int off = ks * 16 + 2 * tq;
        float2 fa0 = *(const float2*)(xa + off);
        float2 fb0 = *(const float2*)(xb + off);
        float2 fa1 = *(const float2*)(xa + off + 8);
        float2 fb1 = *(const float2*)(xb + off + 8);
        union { __half2 h; unsigned u; } a0, a1, a2, a3;
        a0.h = __floats2half2_rn(fa0.x, fa0.y);
        a1.h = __floats2half2_rn(fb0.x, fb0.y);
        a2.h = __floats2half2_rn(fa1.x, fa1.y);
        a3.h = __floats2half2_rn(fb1.x, fb1.y);
        unsigned a[4] = { a0.u, a1.u, a2.u, a3.u };

        unsigned kbase = wsb + (unsigned)(16 * ks) * 128u + wrow;
        #pragma unroll
        for (int pv = 0; pv < 4; pv++) {
            unsigned wb[4];
            ldsm4t(wb, kbase + wsw[pv]);
            mma16816(acc[2 * pv],     a, wb[0], wb[1]);
            mma16816(acc[2 * pv + 1], a, wb[2], wb[3]);
        }
    }

    int ta = (int)(rowa & (Tn - 1));
    __half* dst = (mat == 0) ? g_Q : (mat == 1 ? g_K : g_V);
    long basea = rowa * HSn;
    long baseb = basea + 8 * HSn;

    if (mat <= 1) {
        float sc = (mat == 0) ? QSCALE : 1.f;
        const float* fca = fcos + (long)ta * 32;
        const float* fsa = fsin + (long)ta * 32;
        #pragma unroll
        for (int n = 0; n < 8; n++) {
            int p = n * 4 + tq;
            float ca = fca[p],       sa = fsa[p];
            float cb = fca[256 + p], sb = fsa[256 + p];   // token ta+8
            float c0 = acc[n][0] * sc, c1 = acc[n][1] * sc;
            float c2 = acc[n][2] * sc, c3 = acc[n][3] * sc;
            __half2 ra = __floats2half2_rn(c0 * ca - c1 * sa, c0 * sa + c1 * ca);
            __half2 rb = __floats2half2_rn(c2 * cb - c3 * sb, c2 * sb + c3 * cb);
            *(__half2*)(dst + basea + n * 8 + 2 * tq) = ra;
            *(__half2*)(dst + baseb + n * 8 + 2 * tq) = rb;
        }
    } else {
        #pragma unroll
        for (int n = 0; n < 8; n++) {
            __half2 ra = __floats2half2_rn(acc[n][0], acc[n][1]);
            __half2 rb = __floats2half2_rn(acc[n][2], acc[n][3]);
            *(__half2*)(dst + basea + n * 8 + 2 * tq) = ra;
            *(__half2*)(dst + baseb + n * 8 + 2 * tq) = rb;
        }
    }

    // ---- fused mask-length reduction (blocks 0..Bn-1 only) ----
    if (blockIdx.x < Bn) {
        int b = blockIdx.x;
        const int4* m4 = (const int4*)(mask + b * Tn);
        int sum = 0;
        for (int i = tid; i < Tn / 4; i += 384) {
            int4 v = m4[i];
            sum += v.x + v.y + v.z + v.w;
        }
        #pragma unroll
        for (int off = 16; off > 0; off >>= 1)
            sum += __shfl_down_sync(0xffffffffu, sum, off);
        if (lane == 0) lred[w] = sum;
        __syncthreads();
        if (tid == 0) {
            int s = 0;
            #pragma unroll
            for (int i = 0; i < 12; i++) s += lred[i];
            g_len[b] = s;
        }
    }
}

// ---------------------------------------------------------------------------
// Kernel 2: flash attention, fp16-accum HMMA, BQ=128 (8 warps), split-K x2.
// 3-stage cp.async ring, ONE __syncthreads per tile. Warps skip compute on
// tiles that are fully causal-masked for their rows (kt > qw+15).
// Stores NORMALIZED fp16 partials (o/l) + fp32 (m, l).
// ---------------------------------------------------------------------------
__global__ __launch_bounds__(256, 2) void flash_kernel()
{
    __shared__ __half Ks[3][64 * HSn];
    __shared__ __half Vs[3][64 * HSn];

    int b = blockIdx.y;
    // heavy-first: largest j (most key tiles) gets the earliest blockIdx
    int j = (int)(gridDim.x >> 1) - 1 - (int)(blockIdx.x >> 1);
    int half = blockIdx.x & 1;
    int q0 = j * BQ;
    int tid = threadIdx.x, warp = tid >> 5, lane = tid & 31;
    int g = lane >> 2, t = lane & 3;
    int qw = q0 + warp * 16;
    int len = g_len[b];
    int kend = min(q0 + BQ, len);
    int nt = (kend + 63) >> 6;
    int ti0 = half ? (nt >> 1) : 0;
    int ti1 = half ? nt : (nt >> 1);

    unsigned qf[4][4];
    {
        const __half* Qb = g_Q + ((long)b * Tn + qw) * HSn;
        #pragma unroll
        for (int ks = 0; ks < 4; ks++) {
            qf[ks][0] = *(const unsigned*)(Qb + (g    ) * HSn + ks * 16 + 2 * t);
            qf[ks][1] = *(const unsigned*)(Qb + (g + 8) * HSn + ks * 16 + 2 * t);
            qf[ks][2] = *(const unsigned*)(Qb + (g    ) * HSn + ks * 16 + 2 * t + 8);
            qf[ks][3] = *(const unsigned*)(Qb + (g + 8) * HSn + ks * 16 + 2 * t + 8);
        }
    }

    float o[8][4];
    #pragma unroll
    for (int n = 0; n < 8; n++) { o[n][0] = o[n][1] = o[n][2] = o[n][3] = 0.f; }
    float m0 = -1e30f, m1 = -1e30f, l0 = 0.f, l1 = 0.f;

    unsigned ksb = smem_u32(Ks), vsb = smem_u32(Vs);
    int grp = lane >> 3, r8 = lane & 7;
    unsigned kAdr[4], kSw[4], vAdr[4], vSw[4];
    #pragma unroll
    for (int p = 0; p < 4; p++)
        kAdr[p] = ksb + (unsigned)(16 * p + 8 * (grp >> 1) + r8) * 128u;
    #pragma unroll
    for (int ks = 0; ks < 4; ks++)
        kSw[ks] = (unsigned)(((2 * ks + (grp & 1)) ^ r8) * 16);
    #pragma unroll
    for (int kv = 0; kv < 4; kv++)
        vAdr[kv] = vsb + (unsigned)(16 * kv + 8 * (grp & 1) + r8) * 128u;
    #pragma unroll
    for (int pv = 0; pv < 4; pv++)
        vSw[pv] = (unsigned)(((2 * pv + (grp >> 1)) ^ r8) * 16);

    const __half* Kg = g_K + (long)b * Tn * HSn;
    const __half* Vg = g_V + (long)b * Tn * HSn;

    auto load_tile = [&](int st, int kt) {
        unsigned bo = (unsigned)st * 8192u;
        #pragma unroll
        for (int i = 0; i < 2; i++) {
            int cid = tid + i * 256;               // 0..511
            int row = cid >> 3, c = cid & 7;
            unsigned dst = (unsigned)(row * HSn + ((c ^ (row & 7)) * 8)) * 2u + bo;
            cp_async16(ksb + dst, Kg + (long)(kt + row) * HSn + c * 8);
            cp_async16(vsb + dst, Vg + (long)(kt + row) * HSn + c * 8);
        }
    };

    const __half HM = __float2half_rn(-60000.f);   // finite mask; exp2 underflows to 0

    int buf = 0;
    if (ti0 < ti1) { load_tile(0, ti0 * 64); cp_commit(); }

    for (int ti = ti0; ti < ti1; ti++) {
        int kt = ti * 64;
        int nstage = (buf == 2) ? 0 : buf + 1;
        if (ti + 1 < ti1) {
            load_tile(nstage, (ti + 1) * 64);
            cp_commit();
            cp_wait<1>();
        } else {
            cp_wait<0>();
        }
        __syncthreads();          // single barrier per tile (3-stage ring)

        // fully causal-masked tile for this warp's rows -> skip compute
        // (contribution would be exactly zero: alpha=1, all p=0)
        if (kt <= qw + 15) {
            unsigned bo = (unsigned)buf * 8192u;

            // S = Q K^T in fp16 accum: sreg[n] = {row g half2, row g+8 half2}
            unsigned sreg[8][2];
            #pragma unroll
            for (int n = 0; n < 8; n++) { sreg[n][0] = 0u; sreg[n][1] = 0u; }
            #pragma unroll
            for (int ks = 0; ks < 4; ks++) {
                #pragma unroll
                for (int p = 0; p < 4; p++) {
                    unsigned kb[4];
                    ldsm4(kb, kAdr[p] + bo + kSw[ks]);
                    mma16816h(sreg[2 * p],     qf[ks], kb[0], kb[1]);
                    mma16816h(sreg[2 * p + 1], qf[ks], kb[2], kb[3]);
                }
            }

            // mask (only diagonal / tail tiles)
            bool full = (kt + 63 <= qw) && (kt + 64 <= len);
            if (!full) {
                int rg = qw + g, rg8 = rg + 8;
                #pragma unroll
                for (int n = 0; n < 8; n++) {
                    int k0 = kt + n * 8 + 2 * t;
                    __half2 v0 = *reinterpret_cast<__half2*>(&sreg[n][0]);
                    __half2 v1 = *reinterpret_cast<__half2*>(&sreg[n][1]);
                    if (!(k0     <= rg  && k0     < len)) v0.x = HM;
                    if (!(k0 + 1 <= rg  && k0 + 1 < len)) v0.y = HM;
                    if (!(k0     <= rg8 && k0     < len)) v1.x = HM;
                    if (!(k0 + 1 <= rg8 && k0 + 1 < len)) v1.y = HM;
                    sreg[n][0] = *reinterpret_cast<unsigned*>(&v0);
                    sreg[n][1] = *reinterpret_cast<unsigned*>(&v1);
                }
            }

            // row max via half2 trees (rows g and g+8), finalize fp32
            __half2 h0 = *reinterpret_cast<__half2*>(&sreg[0][0]);
            __half2 h1 = *reinterpret_cast<__half2*>(&sreg[0][1]);
            #pragma unroll
            for (int n = 1; n < 8; n++) {
                h0 = __hmax2(h0, *reinterpret_cast<__half2*>(&sreg[n][0]));
                h1 = __hmax2(h1, *reinterpret_cast<__half2*>(&sreg[n][1]));
            }
            float2 f0 = __half22float2(h0);
            float2 f1 = __half22float2(h1);
            float mr0 = fmaxf(f0.x, f0.y);
            float mr1 = fmaxf(f1.x, f1.y);
            mr0 = fmaxf(mr0, __shfl_xor_sync(0xffffffffu, mr0, 1));
            mr0 = fmaxf(mr0, __shfl_xor_sync(0xffffffffu, mr0, 2));
            mr1 = fmaxf(mr1, __shfl_xor_sync(0xffffffffu, mr1, 1));
            mr1 = fmaxf(mr1, __shfl_xor_sync(0xffffffffu, mr1, 2));

            float mn0 = fmaxf(m0, mr0), mn1 = fmaxf(m1, mr1);
            float a0 = exp2_approx(m0 - mn0), a1 = exp2_approx(m1 - mn1);
            m0 = mn0; m1 = mn1;
            l0 *= a0;  l1 *= a1;

            // p = exp2(s - mn) in-place (f16x2) -> directly the PV A-operand
            __half2 mh0 = __float2half2_rn(mn0);
            __half2 mh1 = __float2half2_rn(mn1);
            float ls0 = 0.f, ls1 = 0.f;
            #pragma unroll
            for (int n = 0; n < 8; n++) {
                __half2 d0 = __hsub2(*reinterpret_cast<__half2*>(&sreg[n][0]), mh0);
                __half2 d1 = __hsub2(*reinterpret_cast<__half2*>(&sreg[n][1]), mh1);
                sreg[n][0] = exp2_h2(*reinterpret_cast<unsigned*>(&d0));
                sreg[n][1] = exp2_h2(*reinterpret_cast<unsigned*>(&d1));
                float2 p0 = __half22float2(*reinterpret_cast<__half2*>(&sreg[n][0]));
                float2 p1 = __half22float2(*reinterpret_cast<__half2*>(&sreg[n][1]));
                ls0 += p0.x + p0.y;
                ls1 += p1.x + p1.y;
            }
            l0 += ls0; l1 += ls1;

            // O += P V  (fp16 accum per tile, fp32 carry across tiles)
            unsigned dreg[8][2];
            #pragma unroll
            for (int n = 0; n < 8; n++) { dreg[n][0] = 0u; dreg[n][1] = 0u; }
            #pragma unroll
            for (int kv = 0; kv < 4; kv++) {
                unsigned pa[4] = { sreg[2 * kv][0], sreg[2 * kv][1],
                                   sreg[2 * kv + 1][0], sreg[2 * kv + 1][1] };
                #pragma unroll
                for (int pv = 0; pv < 4; pv++) {
                    unsigned vb[4];
                    ldsm4t(vb, vAdr[kv] + bo + vSw[pv]);
                    mma16816h(dreg[2 * pv],     pa, vb[0], vb[1]);
                    mma16816h(dreg[2 * pv + 1], pa, vb[2], vb[3]);
                }
            }
            #pragma unroll
            for (int n = 0; n < 8; n++) {
                float2 d0 = __half22float2(*reinterpret_cast<__half2*>(&dreg[n][0]));
                float2 d1 = __half22float2(*reinterpret_cast<__half2*>(&dreg[n][1]));
                o[n][0] = o[n][0] * a0 + d0.x;
                o[n][1] = o[n][1] * a0 + d0.y;
                o[n][2] = o[n][2] * a1 + d1.x;
                o[n][3] = o[n][3] * a1 + d1.y;
            }
        }
        buf = nstage;
    }

    l0 += __shfl_xor_sync(0xffffffffu, l0, 1);
    l0 += __shfl_xor_sync(0xffffffffu, l0, 2);
    l1 += __shfl_xor_sync(0xffffffffu, l1, 1);
    l1 += __shfl_xor_sync(0xffffffffu, l1, 2);

    // normalized fp16 partials (guard: empty range -> l == 0 -> store zeros)
    float inv0 = (l0 > 0.f) ? (1.f / l0) : 0.f;
    float inv1 = (l1 > 0.f) ? (1.f / l1) : 0.f;

    long rbase = (long)b * Tn + qw;
    __half* ob = g_po + ((long)half * Bn * Tn + rbase) * HSn;
    #pragma unroll
    for (int n = 0; n < 8; n++) {
        __half2 v0 = __floats2half2_rn(o[n][0] * inv0, o[n][1] * inv0);
        __half2 v1 = __floats2half2_rn(o[n][2] * inv1, o[n][3] * inv1);
        *(__half2*)(ob + (g    ) * HSn + n * 8 + 2 * t) = v0;
        *(__half2*)(ob + (g + 8) * HSn + n * 8 + 2 * t) = v1;
    }
    if (t == 0) {
        long pr = (long)half * Bn * Tn + rbase;
        g_pm[pr + g]     = m0;  g_pl[pr + g]     = l0;
        g_pm[pr + g + 8] = m1;  g_pl[pr + g + 8] = l1;
    }
}

// ---------------------------------------------------------------------------
// Kernel 3: merge the two split-K partials (normalized fp16) and finalize.
// out = sum_i w_i * o_i_norm, with w_i = l_i * 2^(m_i - ms) / D.
// ---------------------------------------------------------------------------
__global__ __launch_bounds__(256) void merge_kernel(float* __restrict__ out)
{
    int tid = threadIdx.x;
    long r = (long)blockIdx.x * 32 + (tid >> 3);
    int d0 = (tid & 7) * 8;

    float m0 = g_pm[r], l0 = g_pl[r];
    float m1 = g_pm[(long)Bn * Tn + r], l1 = g_pl[(long)Bn * Tn + r];
    float ms = fmaxf(m0, m1);
    float w0 = exp2_approx(m0 - ms) * l0;
    float w1 = exp2_approx(m1 - ms) * l1;
    float inv = 1.f / (w0 + w1);
    w0 *= inv; w1 *= inv;

    long base = r * HSn + d0;
    union { uint4 u; __half2 h[4]; } a, c;
    a.u = *(const uint4*)(g_po + base);
    c.u = *(const uint4*)(g_po + (long)Bn * Tn * HSn + base);

    float4 r0, r1;
    {
        float2 a0 = __half22float2(a.h[0]), c0 = __half22float2(c.h[0]);
        float2 a1 = __half22float2(a.h[1]), c1 = __half22float2(c.h[1]);
        r0.x = a0.x * w0 + c0.x * w1;  r0.y = a0.y * w0 + c0.y * w1;
        r0.z = a1.x * w0 + c1.x * w1;  r0.w = a1.y * w0 + c1.y * w1;
        float2 a2 = __half22float2(a.h[2]), c2 = __half22float2(c.h[2]);
        float2 a3 = __half22float2(a.h[3]), c3 = __half22float2(c.h[3]);
        r1.x = a2.x * w0 + c2.x * w1;  r1.y = a2.y * w0 + c2.y * w1;
        r1.z = a3.x * w0 + c3.x * w1;  r1.w = a3.y * w0 + c3.y * w1;
    }
    float4* po = (float4*)(out + base);
    po[0] = r0;
    po[1] = r1;
}

// ---------------------------------------------------------------------------
extern "C" void kernel_launch(void* const* d_in, const int* in_sizes, int n_in,
                              void* d_out, int out_size) {
    const float* x    = (const float*)d_in[0];
    const float* Wq   = (const float*)d_in[1];
    const float* Wk   = (const float*)d_in[2];
    const float* Wv   = (const float*)d_in[3];
    const float* fcos = (const float*)d_in[4];
    const float* fsin = (const float*)d_in[5];
    const int*   mask = (const int*)d_in[6];
    float* out = (float*)d_out;

    qkv_kernel<<<Bn * Tn / 64, 384>>>(x, Wq, Wk, Wv, fcos, fsin, mask);
    dim3 grid(2 * Tn / BQ, Bn);
    flash_kernel<<<grid, 256>>>();
    merge_kernel<<<Bn * Tn / 32, 256>>>(out);
}

// round 15
// speedup vs baseline: 1.0404x; 1.0404x over previous
#include <cuda_runtime.h>
#include <cuda_fp16.h>
#include <cstdint>
#include <stdint.h>

#define Bn 8
#define Tn 4096
#define Cn 128
#define HSn 64
#define BQ 128

// scale = 1/sqrt(C) folded with log2(e) so we can use ex2.approx
#define QSCALE (0.08838834764831845f * 1.4426950408889634f)

// Scratch (device globals — no allocation allowed in kernel_launch)
__device__ __align__(16) __half g_Q[Bn * Tn * HSn];
__device__ __align__(16) __half g_K[Bn * Tn * HSn];
__device__ __align__(16) __half g_V[Bn * Tn * HSn];
__device__ __align__(16) __half g_po[2 * Bn * Tn * HSn];  // NORMALIZED O partials (fp16)
__device__ float g_pm[2 * Bn * Tn];
__device__ float g_pl[2 * Bn * Tn];
__device__ int g_len[Bn];

__device__ __forceinline__ float exp2_approx(float x) {
    float y;
    asm("ex2.approx.ftz.f32 %0, %1;" : "=f"(y) : "f"(x));
    return y;
}

__device__ __forceinline__ unsigned exp2_h2(unsigned x) {
    unsigned y;
    asm("ex2.approx.f16x2 %0, %1;" : "=r"(y) : "r"(x));
    return y;
}

__device__ __forceinline__ unsigned smem_u32(const void* p) {
    return (unsigned)__cvta_generic_to_shared(p);
}

// fp32-accum HMMA (qkv kernel)
__device__ __forceinline__ void mma16816(float* c, const unsigned* a,
                                         unsigned b0, unsigned b1) {
    asm volatile(
        "mma.sync.aligned.m16n8k16.row.col.f32.f16.f16.f32 "
        "{%0,%1,%2,%3}, {%4,%5,%6,%7}, {%8,%9}, {%0,%1,%2,%3};\n"
        : "+f"(c[0]), "+f"(c[1]), "+f"(c[2]), "+f"(c[3])
        : "r"(a[0]), "r"(a[1]), "r"(a[2]), "r"(a[3]), "r"(b0), "r"(b1));
}

// fp16-accum HMMA (flash kernel) — C fragment == A fragment layout
__device__ __forceinline__ void mma16816h(unsigned* c, const unsigned* a,
                                          unsigned b0, unsigned b1) {
    asm volatile(
        "mma.sync.aligned.m16n8k16.row.col.f16.f16.f16.f16 "
        "{%0,%1}, {%2,%3,%4,%5}, {%6,%7}, {%0,%1};\n"
        : "+r"(c[0]), "+r"(c[1])
        : "r"(a[0]), "r"(a[1]), "r"(a[2]), "r"(a[3]), "r"(b0), "r"(b1));
}

__device__ __forceinline__ void ldsm4(unsigned* r, unsigned addr) {
    asm volatile("ldmatrix.sync.aligned.m8n8.x4.shared.b16 {%0,%1,%2,%3}, [%4];"
                 : "=r"(r[0]), "=r"(r[1]), "=r"(r[2]), "=r"(r[3]) : "r"(addr));
}

__device__ __forceinline__ void ldsm4t(unsigned* r, unsigned addr) {
    asm volatile("ldmatrix.sync.aligned.m8n8.x4.trans.shared.b16 {%0,%1,%2,%3}, [%4];"
                 : "=r"(r[0]), "=r"(r[1]), "=r"(r[2]), "=r"(r[3]) : "r"(addr));
}

__device__ __forceinline__ void cp_async16(unsigned dst, const void* src) {
    asm volatile("cp.async.cg.shared.global [%0], [%1], 16;\n"
                 :: "r"(dst), "l"(src));
}
__device__ __forceinline__ void cp_commit() {
    asm volatile("cp.async.commit_group;\n");
}
template <int N>
__device__ __forceinline__ void cp_wait() {
    asm volatile("cp.async.wait_group %0;\n" :: "n"(N));
}

// ---------------------------------------------------------------------------
// Kernel 0: per-batch valid length (mask is a prefix mask; length = sum)
// ---------------------------------------------------------------------------
__global__ void len_kernel(const int* __restrict__ mask) {
    int b = blockIdx.x;
    int tid = threadIdx.x;
    const int4* m4 = (const int4*)(mask + b * Tn);
    int sum = 0;
    #pragma unroll
    for (int i = 0; i < 4; i++) {
        int4 v = m4[tid + i * 256];
        sum += v.x + v.y + v.z + v.w;
    }
    __shared__ int red[8];
    #pragma unroll
    for (int off = 16; off > 0; off >>= 1)
        sum += __shfl_down_sync(0xffffffffu, sum, off);
    if ((tid & 31) == 0) red[tid >> 5] = sum;
    __syncthreads();
    if (tid == 0) {
        int s = 0;
        #pragma unroll
        for (int w = 0; w < 8; w++) s += red[w];
        g_len[b] = s;
    }
}

// ---------------------------------------------------------------------------
// Kernel 1: fused QKV projection + RoPE via HMMA.
// x staged through smem (fp16, swizzled) once per block; A-fragments via
// non-trans ldmatrix — removes scattered gmem loads and 3x x re-reads.
// ---------------------------------------------------------------------------
__global__ __launch_bounds__(384) void qkv_kernel(
    const float* __restrict__ x,
    const float* __restrict__ Wq,
    const float* __restrict__ Wk,
    const float* __restrict__ Wv,
    const float* __restrict__ fcos,
    const float* __restrict__ fsin)
{
    __shared__ __half Ws[3 * 128 * 64];   // 48KB: [mat][k=128][n=64], swizzled
    __shared__ __half Xs[64 * 128];       // 16KB: [row][k=128] fp16, swizzled per 128B half-row
    int tid = threadIdx.x;

    // W load + fp16 convert + swizzle (3072 16B-chunks)
    #pragma unroll
    for (int i = 0; i < 8; i++) {
        int cid = tid + i * 384;
        int mat = cid >> 10;
        int within = cid & 1023;
        int row = within >> 3, c = within & 7;
        const float* src = (mat == 0 ? Wq : (mat == 1 ? Wk : Wv)) + row * 64 + c * 8;
        float4 f0 = *(const float4*)src;
        float4 f1 = *(const float4*)(src + 4);
        union { __half2 h[4]; uint4 u; } pk;
        pk.h[0] = __floats2half2_rn(f0.x, f0.y);
        pk.h[1] = __floats2half2_rn(f0.z, f0.w);
        pk.h[2] = __floats2half2_rn(f1.x, f1.y);
        pk.h[3] = __floats2half2_rn(f1.z, f1.w);
        int dst = mat * 8192 + row * 64 + ((c ^ (row & 7)) * 8);
        *(uint4*)(Ws + dst) = pk.u;
    }

    // x tile load (64 rows x 128 floats), fp16 convert, swizzled store.
    // 1024 16B-chunks: row = cid>>4, ch = cid&15 (16 chunks of 8 halves/row).
    {
        const float* xg = x + (long)blockIdx.x * 64 * Cn;
        for (int cid = tid; cid < 1024; cid += 384) {
            int row = cid >> 4, ch = cid & 15;
            const float* src = xg + row * Cn + ch * 8;
            float4 f0 = *(const float4*)src;
            float4 f1 = *(const float4*)(src + 4);
            union { __half2 h[4]; uint4 u; } pk;
            pk.h[0] = __floats2half2_rn(f0.x, f0.y);
            pk.h[1] = __floats2half2_rn(f0.z, f0.w);
            pk.h[2] = __floats2half2_rn(f1.x, f1.y);
            pk.h[3] = __floats2half2_rn(f1.z, f1.w);
            int half_ = ch >> 3, c = ch & 7;
            int dst = row * 128 + half_ * 64 + (((c ^ (row & 7))) * 8);
            *(uint4*)(Xs + dst) = pk.u;
        }
    }
    __syncthreads();

    int w = tid >> 5, lane = tid & 31;
    int g = lane >> 2, tq = lane & 3;
    int mat = w >> 2, rg = w & 3;
    long rowa = (long)blockIdx.x * 64 + rg * 16 + g;

    float acc[8][4];
    #pragma unroll
    for (int n = 0; n < 8; n++) { acc[n][0] = acc[n][1] = acc[n][2] = acc[n][3] = 0.f; }

    int grp = lane >> 3, r8 = lane & 7;

    // W-side (B operand) addresses
    unsigned wsb = smem_u32(Ws) + (unsigned)mat * 16384u;
    unsigned wrow = (unsigned)(8 * (grp & 1) + r8) * 128u;
    unsigned wsw[4];
    #pragma unroll
    for (int pv = 0; pv < 4; pv++)
        wsw[pv] = (unsigned)(((2 * pv + (grp >> 1)) ^ r8) * 16);

    // A-side (x) ldmatrix addresses: lane -> row rg*16 + (grp&1)*8 + r8,
    // ki = grp>>1 selects the 16B column half of the 32B k-step.
    int arow = rg * 16 + (grp & 1) * 8 + r8;
    int ki = grp >> 1;
    unsigned xbase = smem_u32(Xs) + (unsigned)(arow * 256);
    unsigned xoff[8];
    #pragma unroll
    for (int ks = 0; ks < 8; ks++) {
        int c16 = ks * 32 + ki * 16;                    // byte col 0..240
        int chunk = (c16 >> 4) & 7;
        xoff[ks] = (unsigned)((c16 & 128) + ((chunk ^ (arow & 7)) * 16));
    }

    #pragma unroll
    for (int ks = 0; ks < 8; ks++) {
        unsigned a[4];
        ldsm4(a, xbase + xoff[ks]);

        unsigned kbase = wsb + (unsigned)(16 * ks) * 128u + wrow;
        #pragma unroll
        for (int pv = 0; pv < 4; pv++) {
            unsigned wb[4];
            ldsm4t(wb, kbase + wsw[pv]);
            mma16816(acc[2 * pv],     a, wb[0], wb[1]);
            mma16816(acc[2 * pv + 1], a, wb[2], wb[3]);
        }
    }

    int ta = (int)(rowa & (Tn - 1));
    __half* dst = (mat == 0) ? g_Q : (mat == 1 ? g_K : g_V);
    long basea = rowa * HSn;
    long baseb = basea + 8 * HSn;

    if (mat <= 1) {
        float sc = (mat == 0) ? QSCALE : 1.f;
        const float* fca = fcos + (long)ta * 32;
        const float* fsa = fsin + (long)ta * 32;
        #pragma unroll
        for (int n = 0; n < 8; n++) {
            int p = n * 4 + tq;
            float ca = fca[p],       sa = fsa[p];
            float cb = fca[256 + p], sb = fsa[256 + p];   // token ta+8
            float c0 = acc[n][0] * sc, c1 = acc[n][1] * sc;
            float c2 = acc[n][2] * sc, c3 = acc[n][3] * sc;
            __half2 ra = __floats2half2_rn(c0 * ca - c1 * sa, c0 * sa + c1 * ca);
            __half2 rb = __floats2half2_rn(c2 * cb - c3 * sb, c2 * sb + c3 * cb);
            *(__half2*)(dst + basea + n * 8 + 2 * tq) = ra;
            *(__half2*)(dst + baseb + n * 8 + 2 * tq) = rb;
        }
    } else {
        #pragma unroll
        for (int n = 0; n < 8; n++) {
            __half2 ra = __floats2half2_rn(acc[n][0], acc[n][1]);
            __half2 rb = __floats2half2_rn(acc[n][2], acc[n][3]);
            *(__half2*)(dst + basea + n * 8 + 2 * tq) = ra;
            *(__half2*)(dst + baseb + n * 8 + 2 * tq) = rb;
        }
    }
}

// ---------------------------------------------------------------------------
// Kernel 2: flash attention, fp16-accum HMMA, BQ=128 (8 warps), split-K x2.
// 3-stage cp.async ring, ONE __syncthreads per tile.
// Stores NORMALIZED fp16 partials (o/l) + fp32 (m, l).
// ---------------------------------------------------------------------------
__global__ __launch_bounds__(256, 2) void flash_kernel()
{
    __shared__ __half Ks[3][64 * HSn];
    __shared__ __half Vs[3][64 * HSn];

    int b = blockIdx.y;
    // heavy-first: largest j (most key tiles) gets the earliest blockIdx
    int j = (int)(gridDim.x >> 1) - 1 - (int)(blockIdx.x >> 1);
    int half = blockIdx.x & 1;
    int q0 = j * BQ;
    int tid = threadIdx.x, warp = tid >> 5, lane = tid & 31;
    int g = lane >> 2, t = lane & 3;
    int qw = q0 + warp * 16;
    int len = g_len[b];
    int kend = min(q0 + BQ, len);
    int nt = (kend + 63) >> 6;
    int ti0 = half ? (nt >> 1) : 0;
    int ti1 = half ? nt : (nt >> 1);

    unsigned qf[4][4];
    {
        const __half* Qb = g_Q + ((long)b * Tn + qw) * HSn;
        #pragma unroll
        for (int ks = 0; ks < 4; ks++) {
            qf[ks][0] = *(const unsigned*)(Qb + (g    ) * HSn + ks * 16 + 2 * t);
            qf[ks][1] = *(const unsigned*)(Qb + (g + 8) * HSn + ks * 16 + 2 * t);
            qf[ks][2] = *(const unsigned*)(Qb + (g    ) * HSn + ks * 16 + 2 * t + 8);
            qf[ks][3] = *(const unsigned*)(Qb + (g + 8) * HSn + ks * 16 + 2 * t + 8);
        }
    }

    float o[8][4];
    #pragma unroll
    for (int n = 0; n < 8; n++) { o[n][0] = o[n][1] = o[n][2] = o[n][3] = 0.f; }
    float m0 = -1e30f, m1 = -1e30f, l0 = 0.f, l1 = 0.f;

    unsigned ksb = smem_u32(Ks), vsb = smem_u32(Vs);
    int grp = lane >> 3, r8 = lane & 7;
    unsigned kAdr[4], kSw[4], vAdr[4], vSw[4];
    #pragma unroll
    for (int p = 0; p < 4; p++)
        kAdr[p] = ksb + (unsigned)(16 * p + 8 * (grp >> 1) + r8) * 128u;
    #pragma unroll
    for (int ks = 0; ks < 4; ks++)
        kSw[ks] = (unsigned)(((2 * ks + (grp & 1)) ^ r8) * 16);
    #pragma unroll
    for (int kv = 0; kv < 4; kv++)
        vAdr[kv] = vsb + (unsigned)(16 * kv + 8 * (grp & 1) + r8) * 128u;
    #pragma unroll
    for (int pv = 0; pv < 4; pv++)
        vSw[pv] = (unsigned)(((2 * pv + (grp >> 1)) ^ r8) * 16);

    const __half* Kg = g_K + (long)b * Tn * HSn;
    const __half* Vg = g_V + (long)b * Tn * HSn;

    auto load_tile = [&](int st, int kt) {
        unsigned bo = (unsigned)st * 8192u;
        #pragma unroll
        for (int i = 0; i < 2; i++) {
            int cid = tid + i * 256;               // 0..511
            int row = cid >> 3, c = cid & 7;
            unsigned dst = (unsigned)(row * HSn + ((c ^ (row & 7)) * 8)) * 2u + bo;
            cp_async16(ksb + dst, Kg + (long)(kt + row) * HSn + c * 8);
            cp_async16(vsb + dst, Vg + (long)(kt + row) * HSn + c * 8);
        }
    };

    const __half HM = __float2half_rn(-60000.f);   // finite mask; exp2 underflows to 0

    int buf = 0;
    if (ti0 < ti1) { load_tile(0, ti0 * 64); cp_commit(); }

    for (int ti = ti0; ti < ti1; ti++) {
        int kt = ti * 64;
        int nstage = (buf == 2) ? 0 : buf + 1;
        if (ti + 1 < ti1) {
            load_tile(nstage, (ti + 1) * 64);
            cp_commit();
            cp_wait<1>();
        } else {
            cp_wait<0>();
        }
        __syncthreads();          // single barrier per tile (3-stage ring)

        unsigned bo = (unsigned)buf * 8192u;

        // S = Q K^T in fp16 accum: sreg[n] = {row g half2, row g+8 half2}
        unsigned sreg[8][2];
        #pragma unroll
        for (int n = 0; n < 8; n++) { sreg[n][0] = 0u; sreg[n][1] = 0u; }
        #pragma unroll
        for (int ks = 0; ks < 4; ks++) {
            #pragma unroll
            for (int p = 0; p < 4; p++) {
                unsigned kb[4];
                ldsm4(kb, kAdr[p] + bo + kSw[ks]);
                mma16816h(sreg[2 * p],     qf[ks], kb[0], kb[1]);
                mma16816h(sreg[2 * p + 1], qf[ks], kb[2], kb[3]);
            }
        }

        // mask (only diagonal / tail tiles)
        bool full = (kt + 63 <= qw) && (kt + 64 <= len);
        if (!full) {
            int rg = qw + g, rg8 = rg + 8;
            #pragma unroll
            for (int n = 0; n < 8; n++) {
                int k0 = kt + n * 8 + 2 * t;
                __half2 v0 = *reinterpret_cast<__half2*>(&sreg[n][0]);
                __half2 v1 = *reinterpret_cast<__half2*>(&sreg[n][1]);
                if (!(k0     <= rg  && k0     < len)) v0.x = HM;
                if (!(k0 + 1 <= rg  && k0 + 1 < len)) v0.y = HM;
                if (!(k0     <= rg8 && k0     < len)) v1.x = HM;
                if (!(k0 + 1 <= rg8 && k0 + 1 < len)) v1.y = HM;
                sreg[n][0] = *reinterpret_cast<unsigned*>(&v0);
                sreg[n][1] = *reinterpret_cast<unsigned*>(&v1);
            }
        }

        // row max via half2 trees (rows g and g+8), finalize fp32
        {
            __half2 h0 = *reinterpret_cast<__half2*>(&sreg[0][0]);
            __half2 h1 = *reinterpret_cast<__half2*>(&sreg[0][1]);
            #pragma unroll
            for (int n = 1; n < 8; n++) {
                h0 = __hmax2(h0, *reinterpret_cast<__half2*>(&sreg[n][0]));
                h1 = __hmax2(h1, *reinterpret_cast<__half2*>(&sreg[n][1]));
            }
            float2 f0 = __half22float2(h0);
            float2 f1 = __half22float2(h1);
            float mr0 = fmaxf(f0.x, f0.y);
            float mr1 = fmaxf(f1.x, f1.y);
            mr0 = fmaxf(mr0, __shfl_xor_sync(0xffffffffu, mr0, 1));
            mr0 = fmaxf(mr0, __shfl_xor_sync(0xffffffffu, mr0, 2));
            mr1 = fmaxf(mr1, __shfl_xor_sync(0xffffffffu, mr1, 1));
            mr1 = fmaxf(mr1, __shfl_xor_sync(0xffffffffu, mr1, 2));

            float mn0 = fmaxf(m0, mr0), mn1 = fmaxf(m1, mr1);
            float a0 = exp2_approx(m0 - mn0), a1 = exp2_approx(m1 - mn1);
            m0 = mn0; m1 = mn1;
            l0 *= a0;  l1 *= a1;

            // p = exp2(s - mn) in-place (f16x2) -> directly the PV A-operand
            __half2 mh0 = __float2half2_rn(mn0);
            __half2 mh1 = __float2half2_rn(mn1);
            float ls0 = 0.f, ls1 = 0.f;
            #pragma unroll
            for (int n = 0; n < 8; n++) {
                __half2 d0 = __hsub2(*reinterpret_cast<__half2*>(&sreg[n][0]), mh0);
                __half2 d1 = __hsub2(*reinterpret_cast<__half2*>(&sreg[n][1]), mh1);
                sreg[n][0] = exp2_h2(*reinterpret_cast<unsigned*>(&d0));
                sreg[n][1] = exp2_h2(*reinterpret_cast<unsigned*>(&d1));
                float2 p0 = __half22float2(*reinterpret_cast<__half2*>(&sreg[n][0]));
                float2 p1 = __half22float2(*reinterpret_cast<__half2*>(&sreg[n][1]));
                ls0 += p0.x + p0.y;
                ls1 += p1.x + p1.y;
            }
            l0 += ls0; l1 += ls1;

            // O += P V  (fp16 accum per tile, fp32 carry across tiles)
            unsigned dreg[8][2];
            #pragma unroll
            for (int n = 0; n < 8; n++) { dreg[n][0] = 0u; dreg[n][1] = 0u; }
            #pragma unroll
            for (int kv = 0; kv < 4; kv++) {
                unsigned pa[4] = { sreg[2 * kv][0], sreg[2 * kv][1],
                                   sreg[2 * kv + 1][0], sreg[2 * kv + 1][1] };
                #pragma unroll
                for (int pv = 0; pv < 4; pv++) {
                    unsigned vb[4];
                    ldsm4t(vb, vAdr[kv] + bo + vSw[pv]);
                    mma16816h(dreg[2 * pv],     pa, vb[0], vb[1]);
                    mma16816h(dreg[2 * pv + 1], pa, vb[2], vb[3]);
                }
            }
            #pragma unroll
            for (int n = 0; n < 8; n++) {
                float2 d0 = __half22float2(*reinterpret_cast<__half2*>(&dreg[n][0]));
                float2 d1 = __half22float2(*reinterpret_cast<__half2*>(&dreg[n][1]));
                o[n][0] = o[n][0] * a0 + d0.x;
                o[n][1] = o[n][1] * a0 + d0.y;
                o[n][2] = o[n][2] * a1 + d1.x;
                o[n][3] = o[n][3] * a1 + d1.y;
            }
        }
        buf = nstage;
    }

    l0 += __shfl_xor_sync(0xffffffffu, l0, 1);
    l0 += __shfl_xor_sync(0xffffffffu, l0, 2);
    l1 += __shfl_xor_sync(0xffffffffu, l1, 1);
    l1 += __shfl_xor_sync(0xffffffffu, l1, 2);

    // normalized fp16 partials (guard: empty range -> l == 0 -> store zeros)
    float inv0 = (l0 > 0.f) ? (1.f / l0) : 0.f;
    float inv1 = (l1 > 0.f) ? (1.f / l1) : 0.f;

    long rbase = (long)b * Tn + qw;
    __half* ob = g_po + ((long)half * Bn * Tn + rbase) * HSn;
    #pragma unroll
    for (int n = 0; n < 8; n++) {
        __half2 v0 = __floats2half2_rn(o[n][0] * inv0, o[n][1] * inv0);
        __half2 v1 = __floats2half2_rn(o[n][2] * inv1, o[n][3] * inv1);
        *(__half2*)(ob + (g    ) * HSn + n * 8 + 2 * t) = v0;
        *(__half2*)(ob + (g + 8) * HSn + n * 8 + 2 * t) = v1;
    }
    if (t == 0) {
        long pr = (long)half * Bn * Tn + rbase;
        g_pm[pr + g]     = m0;  g_pl[pr + g]     = l0;
        g_pm[pr + g + 8] = m1;  g_pl[pr + g + 8] = l1;
    }
}

// ---------------------------------------------------------------------------
// Kernel 3: merge the two split-K partials (normalized fp16) and finalize.
// out = sum_i w_i * o_i_norm, with w_i = l_i * 2^(m_i - ms) / D.
// ---------------------------------------------------------------------------
__global__ __launch_bounds__(256) void merge_kernel(float* __restrict__ out)
{
    int tid = threadIdx.x;
    long r = (long)blockIdx.x * 32 + (tid >> 3);
    int d0 = (tid & 7) * 8;

    float m0 = g_pm[r], l0 = g_pl[r];
    float m1 = g_pm[(long)Bn * Tn + r], l1 = g_pl[(long)Bn * Tn + r];
    float ms = fmaxf(m0, m1);
    float w0 = exp2_approx(m0 - ms) * l0;
    float w1 = exp2_approx(m1 - ms) * l1;
    float inv = 1.f / (w0 + w1);
    w0 *= inv; w1 *= inv;

    long base = r * HSn + d0;
    union { uint4 u; __half2 h[4]; } a, c;
    a.u = *(const uint4*)(g_po + base);
    c.u = *(const uint4*)(g_po + (long)Bn * Tn * HSn + base);

    float4 r0, r1;
    {
        float2 a0 = __half22float2(a.h[0]), c0 = __half22float2(c.h[0]);
        float2 a1 = __half22float2(a.h[1]), c1 = __half22float2(c.h[1]);
        r0.x = a0.x * w0 + c0.x * w1;  r0.y = a0.y * w0 + c0.y * w1;
        r0.z = a1.x * w0 + c1.x * w1;  r0.w = a1.y * w0 + c1.y * w1;
        float2 a2 = __half22float2(a.h[2]), c2 = __half22float2(c.h[2]);
        float2 a3 = __half22float2(a.h[3]), c3 = __half22float2(c.h[3]);
        r1.x = a2.x * w0 + c2.x * w1;  r1.y = a2.y * w0 + c2.y * w1;
        r1.z = a3.x * w0 + c3.x * w1;  r1.w = a3.y * w0 + c3.y * w1;
    }
    float4* po = (float4*)(out + base);
    po[0] = r0;
    po[1] = r1;
}

// ---------------------------------------------------------------------------
extern "C" void kernel_launch(void* const* d_in, const int* in_sizes, int n_in,
                              void* d_out, int out_size) {
    const float* x    = (const float*)d_in[0];
    const float* Wq   = (const float*)d_in[1];
    const float* Wk   = (const float*)d_in[2];
    const float* Wv   = (const float*)d_in[3];
    const float* fcos = (const float*)d_in[4];
    const float* fsin = (const float*)d_in[5];
    const int*   mask = (const int*)d_in[6];
    float* out = (float*)d_out;

    len_kernel<<<Bn, 256>>>(mask);
    qkv_kernel<<<Bn * Tn / 64, 384>>>(x, Wq, Wk, Wv, fcos, fsin);
    dim3 grid(2 * Tn / BQ, Bn);
    flash_kernel<<<grid, 256>>>();
    merge_kernel<<<Bn * Tn / 32, 256>>>(out);
}

// round 16
// speedup vs baseline: 1.5402x; 1.4804x over previous
#include <cuda_runtime.h>
#include <cuda_fp16.h>
#include <cstdint>
#include <stdint.h>

#define Bn 8
#define Tn 4096
#define Cn 128
#define HSn 64
#define BQ 128

// scale = 1/sqrt(C) folded with log2(e) so we can use ex2.approx
#define QSCALE (0.08838834764831845f * 1.4426950408889634f)

// Scratch (device globals — no allocation allowed in kernel_launch)
__device__ __align__(16) __half g_Q[Bn * Tn * HSn];
__device__ __align__(16) __half g_K[Bn * Tn * HSn];
__device__ __align__(16) __half g_V[Bn * Tn * HSn];
__device__ __align__(16) __half g_po[2 * Bn * Tn * HSn];  // NORMALIZED O partials (fp16)
__device__ float g_pm[2 * Bn * Tn];
__device__ float g_pl[2 * Bn * Tn];
__device__ int g_len[Bn];

__device__ __forceinline__ float exp2_approx(float x) {
    float y;
    asm("ex2.approx.ftz.f32 %0, %1;" : "=f"(y) : "f"(x));
    return y;
}

__device__ __forceinline__ unsigned exp2_h2(unsigned x) {
    unsigned y;
    asm("ex2.approx.f16x2 %0, %1;" : "=r"(y) : "r"(x));
    return y;
}

__device__ __forceinline__ unsigned smem_u32(const void* p) {
    return (unsigned)__cvta_generic_to_shared(p);
}

// fp32-accum HMMA (qkv kernel)
__device__ __forceinline__ void mma16816(float* c, const unsigned* a,
                                         unsigned b0, unsigned b1) {
    asm volatile(
        "mma.sync.aligned.m16n8k16.row.col.f32.f16.f16.f32 "
        "{%0,%1,%2,%3}, {%4,%5,%6,%7}, {%8,%9}, {%0,%1,%2,%3};\n"
        : "+f"(c[0]), "+f"(c[1]), "+f"(c[2]), "+f"(c[3])
        : "r"(a[0]), "r"(a[1]), "r"(a[2]), "r"(a[3]), "r"(b0), "r"(b1));
}

// fp16-accum HMMA (flash kernel) — C fragment == A fragment layout
__device__ __forceinline__ void mma16816h(unsigned* c, const unsigned* a,
                                          unsigned b0, unsigned b1) {
    asm volatile(
        "mma.sync.aligned.m16n8k16.row.col.f16.f16.f16.f16 "
        "{%0,%1}, {%2,%3,%4,%5}, {%6,%7}, {%0,%1};\n"
        : "+r"(c[0]), "+r"(c[1])
        : "r"(a[0]), "r"(a[1]), "r"(a[2]), "r"(a[3]), "r"(b0), "r"(b1));
}

__device__ __forceinline__ void ldsm4(unsigned* r, unsigned addr) {
    asm volatile("ldmatrix.sync.aligned.m8n8.x4.shared.b16 {%0,%1,%2,%3}, [%4];"
                 : "=r"(r[0]), "=r"(r[1]), "=r"(r[2]), "=r"(r[3]) : "r"(addr));
}

__device__ __forceinline__ void ldsm4t(unsigned* r, unsigned addr) {
    asm volatile("ldmatrix.sync.aligned.m8n8.x4.trans.shared.b16 {%0,%1,%2,%3}, [%4];"
                 : "=r"(r[0]), "=r"(r[1]), "=r"(r[2]), "=r"(r[3]) : "r"(addr));
}

__device__ __forceinline__ void cp_async16(unsigned dst, const void* src) {
    asm volatile("cp.async.cg.shared.global [%0], [%1], 16;\n"
                 :: "r"(dst), "l"(src));
}
__device__ __forceinline__ void cp_commit() {
    asm volatile("cp.async.commit_group;\n");
}
template <int N>
__device__ __forceinline__ void cp_wait() {
    asm volatile("cp.async.wait_group %0;\n" :: "n"(N));
}

// ---------------------------------------------------------------------------
// Kernel 1: fused QKV projection + RoPE via HMMA (fp32 accum for accuracy).
// Blocks 0..Bn-1 also reduce the padding mask for their batch (replaces the
// standalone len_kernel launch; measured cost ~1-2us vs 10.9us launch).
// ---------------------------------------------------------------------------
__global__ __launch_bounds__(384) void qkv_kernel(
    const float* __restrict__ x,
    const float* __restrict__ Wq,
    const float* __restrict__ Wk,
    const float* __restrict__ Wv,
    const float* __restrict__ fcos,
    const float* __restrict__ fsin,
    const int* __restrict__ mask)
{
    __shared__ __half Ws[3 * 128 * 64];     // 48KB: [mat][k=128][n=64], swizzled
    __shared__ int lred[12];
    int tid = threadIdx.x;

    #pragma unroll
    for (int i = 0; i < 8; i++) {
        int cid = tid + i * 384;
        int mat = cid >> 10;
        int within = cid & 1023;
        int row = within >> 3, c = within & 7;
        const float* src = (mat == 0 ? Wq : (mat == 1 ? Wk : Wv)) + row * 64 + c * 8;
        float4 f0 = *(const float4*)src;
        float4 f1 = *(const float4*)(src + 4);
        union { __half2 h[4]; uint4 u; } pk;
        pk.h[0] = __floats2half2_rn(f0.x, f0.y);
        pk.h[1] = __floats2half2_rn(f0.z, f0.w);
        pk.h[2] = __floats2half2_rn(f1.x, f1.y);
        pk.h[3] = __floats2half2_rn(f1.z, f1.w);
        int dst = mat * 8192 + row * 64 + ((c ^ (row & 7)) * 8);
        *(uint4*)(Ws + dst) = pk.u;
    }
    __syncthreads();

    int w = tid >> 5, lane = tid & 31;
    int g = lane >> 2, tq = lane & 3;
    int mat = w >> 2, rg = w & 3;
    long rowa = (long)blockIdx.x * 64 + rg * 16 + g;

    float acc[8][4];
    #pragma unroll
    for (int n = 0; n < 8; n++) { acc[n][0] = acc[n][1] = acc[n][2] = acc[n][3] = 0.f; }

    unsigned wsb = smem_u32(Ws) + (unsigned)mat * 16384u;
    int grp = lane >> 3, r8 = lane & 7;
    unsigned wrow = (unsigned)(8 * (grp & 1) + r8) * 128u;
    unsigned wsw[4];
    #pragma unroll
    for (int pv = 0; pv < 4; pv++)
        wsw[pv] = (unsigned)(((2 * pv + (grp >> 1)) ^ r8) * 16);

    const float* xa = x + rowa * Cn;
    const float* xb = xa + 8 * Cn;

    #pragma unroll
    for (int ks = 0; ks < 8; ks++) {
        int off = ks * 16 + 2 * tq;
        float2 fa0 = *(const float2*)(xa + off);
        float2 fb0 = *(const float2*)(xb + off);
        float2 fa1 = *(const float2*)(xa + off + 8);
        float2 fb1 = *(const float2*)(xb + off + 8);
        union { __half2 h; unsigned u; } a0, a1, a2, a3;
        a0.h = __floats2half2_rn(fa0.x, fa0.y);
        a1.h = __floats2half2_rn(fb0.x, fb0.y);
        a2.h = __floats2half2_rn(fa1.x, fa1.y);
        a3.h = __floats2half2_rn(fb1.x, fb1.y);
        unsigned a[4] = { a0.u, a1.u, a2.u, a3.u };

        unsigned kbase = wsb + (unsigned)(16 * ks) * 128u + wrow;
        #pragma unroll
        for (int pv = 0; pv < 4; pv++) {
            unsigned wb[4];
            ldsm4t(wb, kbase + wsw[pv]);
            mma16816(acc[2 * pv],     a, wb[0], wb[1]);
            mma16816(acc[2 * pv + 1], a, wb[2], wb[3]);
        }
    }

    int ta = (int)(rowa & (Tn - 1));
    __half* dst = (mat == 0) ? g_Q : (mat == 1 ? g_K : g_V);
    long basea = rowa * HSn;
    long baseb = basea + 8 * HSn;

    if (mat <= 1) {
        float sc = (mat == 0) ? QSCALE : 1.f;
        const float* fca = fcos + (long)ta * 32;
        const float* fsa = fsin + (long)ta * 32;
        #pragma unroll
        for (int n = 0; n < 8; n++) {
            int p = n * 4 + tq;
            float ca = fca[p],       sa = fsa[p];
            float cb = fca[256 + p], sb = fsa[256 + p];   // token ta+8
            float c0 = acc[n][0] * sc, c1 = acc[n][1] * sc;
            float c2 = acc[n][2] * sc, c3 = acc[n][3] * sc;
            __half2 ra = __floats2half2_rn(c0 * ca - c1 * sa, c0 * sa + c1 * ca);
            __half2 rb = __floats2half2_rn(c2 * cb - c3 * sb, c2 * sb + c3 * cb);
            *(__half2*)(dst + basea + n * 8 + 2 * tq) = ra;
            *(__half2*)(dst + baseb + n * 8 + 2 * tq) = rb;
        }
    } else {
        #pragma unroll
        for (int n = 0; n < 8; n++) {
            __half2 ra = __floats2half2_rn(acc[n][0], acc[n][1]);
            __half2 rb = __floats2half2_rn(acc[n][2], acc[n][3]);
            *(__half2*)(dst + basea + n * 8 + 2 * tq) = ra;
            *(__half2*)(dst + baseb + n * 8 + 2 * tq) = rb;
        }
    }

    // ---- fused mask-length reduction (blocks 0..Bn-1 only) ----
    if (blockIdx.x < Bn) {
        int b = blockIdx.x;
        const int4* m4 = (const int4*)(mask + b * Tn);
        int sum = 0;
        for (int i = tid; i < Tn / 4; i += 384) {
            int4 v = m4[i];
            sum += v.x + v.y + v.z + v.w;
        }
        #pragma unroll
        for (int off = 16; off > 0; off >>= 1)
            sum += __shfl_down_sync(0xffffffffu, sum, off);
        if (lane == 0) lred[w] = sum;
        __syncthreads();
        if (tid == 0) {
            int s = 0;
            #pragma unroll
            for (int i = 0; i < 12; i++) s += lred[i];
            g_len[b] = s;
        }
    }
}

// ---------------------------------------------------------------------------
// Kernel 2: flash attention, fp16-accum HMMA, BQ=128 (8 warps), split-K x2.
// 3-stage cp.async ring, ONE __syncthreads per tile.
// Stores NORMALIZED fp16 partials (o/l) + fp32 (m, l).
// (Byte-identical to the 102.9us R12 version — no skip branch.)
// ---------------------------------------------------------------------------
__global__ __launch_bounds__(256, 2) void flash_kernel()
{
    __shared__ __half Ks[3][64 * HSn];
    __shared__ __half Vs[3][64 * HSn];

    int b = blockIdx.y;
    // heavy-first: largest j (most key tiles) gets the earliest blockIdx
    int j = (int)(gridDim.x >> 1) - 1 - (int)(blockIdx.x >> 1);
    int half = blockIdx.x & 1;
    int q0 = j * BQ;
    int tid = threadIdx.x, warp = tid >> 5, lane = tid & 31;
    int g = lane >> 2, t = lane & 3;
    int qw = q0 + warp * 16;
    int len = g_len[b];
    int kend = min(q0 + BQ, len);
    int nt = (kend + 63) >> 6;
    int ti0 = half ? (nt >> 1) : 0;
    int ti1 = half ? nt : (nt >> 1);

    unsigned qf[4][4];
    {
        const __half* Qb = g_Q + ((long)b * Tn + qw) * HSn;
        #pragma unroll
        for (int ks = 0; ks < 4; ks++) {
            qf[ks][0] = *(const unsigned*)(Qb + (g    ) * HSn + ks * 16 + 2 * t);
            qf[ks][1] = *(const unsigned*)(Qb + (g + 8) * HSn + ks * 16 + 2 * t);
            qf[ks][2] = *(const unsigned*)(Qb + (g    ) * HSn + ks * 16 + 2 * t + 8);
            qf[ks][3] = *(const unsigned*)(Qb + (g + 8) * HSn + ks * 16 + 2 * t + 8);
        }
    }

    float o[8][4];
    #pragma unroll
    for (int n = 0; n < 8; n++) { o[n][0] = o[n][1] = o[n][2] = o[n][3] = 0.f; }
    float m0 = -1e30f, m1 = -1e30f, l0 = 0.f, l1 = 0.f;

    unsigned ksb = smem_u32(Ks), vsb = smem_u32(Vs);
    int grp = lane >> 3, r8 = lane & 7;
    unsigned kAdr[4], kSw[4], vAdr[4], vSw[4];
    #pragma unroll
    for (int p = 0; p < 4; p++)
        kAdr[p] = ksb + (unsigned)(16 * p + 8 * (grp >> 1) + r8) * 128u;
    #pragma unroll
    for (int ks = 0; ks < 4; ks++)
        kSw[ks] = (unsigned)(((2 * ks + (grp & 1)) ^ r8) * 16);
    #pragma unroll
    for (int kv = 0; kv < 4; kv++)
        vAdr[kv] = vsb + (unsigned)(16 * kv + 8 * (grp & 1) + r8) * 128u;
    #pragma unroll
    for (int pv = 0; pv < 4; pv++)
        vSw[pv] = (unsigned)(((2 * pv + (grp >> 1)) ^ r8) * 16);

    const __half* Kg = g_K + (long)b * Tn * HSn;
    const __half* Vg = g_V + (long)b * Tn * HSn;

    auto load_tile = [&](int st, int kt) {
        unsigned bo = (unsigned)st * 8192u;
        #pragma unroll
        for (int i = 0; i < 2; i++) {
            int cid = tid + i * 256;               // 0..511
            int row = cid >> 3, c = cid & 7;
            unsigned dst = (unsigned)(row * HSn + ((c ^ (row & 7)) * 8)) * 2u + bo;
            cp_async16(ksb + dst, Kg + (long)(kt + row) * HSn + c * 8);
            cp_async16(vsb + dst, Vg + (long)(kt + row) * HSn + c * 8);
        }
    };

    const __half HM = __float2half_rn(-60000.f);   // finite mask; exp2 underflows to 0

    int buf = 0;
    if (ti0 < ti1) { load_tile(0, ti0 * 64); cp_commit(); }

    for (int ti = ti0; ti < ti1; ti++) {
        int kt = ti * 64;
        int nstage = (buf == 2) ? 0 : buf + 1;
        if (ti + 1 < ti1) {
            load_tile(nstage, (ti + 1) * 64);
            cp_commit();
            cp_wait<1>();
        } else {
            cp_wait<0>();
        }
        __syncthreads();          // single barrier per tile (3-stage ring)

        unsigned bo = (unsigned)buf * 8192u;

        // S = Q K^T in fp16 accum: sreg[n] = {row g half2, row g+8 half2}
        unsigned sreg[8][2];
        #pragma unroll
        for (int n = 0; n < 8; n++) { sreg[n][0] = 0u; sreg[n][1] = 0u; }
        #pragma unroll
        for (int ks = 0; ks < 4; ks++) {
            #pragma unroll
            for (int p = 0; p < 4; p++) {
                unsigned kb[4];
                ldsm4(kb, kAdr[p] + bo + kSw[ks]);
                mma16816h(sreg[2 * p],     qf[ks], kb[0], kb[1]);
                mma16816h(sreg[2 * p + 1], qf[ks], kb[2], kb[3]);
            }
        }

        // mask (only diagonal / tail tiles)
        bool full = (kt + 63 <= qw) && (kt + 64 <= len);
        if (!full) {
            int rg = qw + g, rg8 = rg + 8;
            #pragma unroll
            for (int n = 0; n < 8; n++) {
                int k0 = kt + n * 8 + 2 * t;
                __half2 v0 = *reinterpret_cast<__half2*>(&sreg[n][0]);
                __half2 v1 = *reinterpret_cast<__half2*>(&sreg[n][1]);
                if (!(k0     <= rg  && k0     < len)) v0.x = HM;
                if (!(k0 + 1 <= rg  && k0 + 1 < len)) v0.y = HM;
                if (!(k0     <= rg8 && k0     < len)) v1.x = HM;
                if (!(k0 + 1 <= rg8 && k0 + 1 < len)) v1.y = HM;
                sreg[n][0] = *reinterpret_cast<unsigned*>(&v0);
                sreg[n][1] = *reinterpret_cast<unsigned*>(&v1);
            }
        }

        // row max via half2 trees (rows g and g+8), finalize fp32
        {
            __half2 h0 = *reinterpret_cast<__half2*>(&sreg[0][0]);
            __half2 h1 = *reinterpret_cast<__half2*>(&sreg[0][1]);
            #pragma unroll
            for (int n = 1; n < 8; n++) {
                h0 = __hmax2(h0, *reinterpret_cast<__half2*>(&sreg[n][0]));
                h1 = __hmax2(h1, *reinterpret_cast<__half2*>(&sreg[n][1]));
            }
            float2 f0 = __half22float2(h0);
            float2 f1 = __half22float2(h1);
            float mr0 = fmaxf(f0.x, f0.y);
            float mr1 = fmaxf(f1.x, f1.y);
            mr0 = fmaxf(mr0, __shfl_xor_sync(0xffffffffu, mr0, 1));
            mr0 = fmaxf(mr0, __shfl_xor_sync(0xffffffffu, mr0, 2));
            mr1 = fmaxf(mr1, __shfl_xor_sync(0xffffffffu, mr1, 1));
            mr1 = fmaxf(mr1, __shfl_xor_sync(0xffffffffu, mr1, 2));

            float mn0 = fmaxf(m0, mr0), mn1 = fmaxf(m1, mr1);
            float a0 = exp2_approx(m0 - mn0), a1 = exp2_approx(m1 - mn1);
            m0 = mn0; m1 = mn1;
            l0 *= a0;  l1 *= a1;

            // p = exp2(s - mn) in-place (f16x2) -> directly the PV A-operand
            __half2 mh0 = __float2half2_rn(mn0);
            __half2 mh1 = __float2half2_rn(mn1);
            float ls0 = 0.f, ls1 = 0.f;
            #pragma unroll
            for (int n = 0; n < 8; n++) {
                __half2 d0 = __hsub2(*reinterpret_cast<__half2*>(&sreg[n][0]), mh0);
                __half2 d1 = __hsub2(*reinterpret_cast<__half2*>(&sreg[n][1]), mh1);
                sreg[n][0] = exp2_h2(*reinterpret_cast<unsigned*>(&d0));
                sreg[n][1] = exp2_h2(*reinterpret_cast<unsigned*>(&d1));
                float2 p0 = __half22float2(*reinterpret_cast<__half2*>(&sreg[n][0]));
                float2 p1 = __half22float2(*reinterpret_cast<__half2*>(&sreg[n][1]));
                ls0 += p0.x + p0.y;
                ls1 += p1.x + p1.y;
            }
            l0 += ls0; l1 += ls1;

            // O += P V  (fp16 accum per tile, fp32 carry across tiles)
            unsigned dreg[8][2];
            #pragma unroll
            for (int n = 0; n < 8; n++) { dreg[n][0] = 0u; dreg[n][1] = 0u; }
            #pragma unroll
            for (int kv = 0; kv < 4; kv++) {
                unsigned pa[4] = { sreg[2 * kv][0], sreg[2 * kv][1],
                                   sreg[2 * kv + 1][0], sreg[2 * kv + 1][1] };
                #pragma unroll
                for (int pv = 0; pv < 4; pv++) {
                    unsigned vb[4];
                    ldsm4t(vb, vAdr[kv] + bo + vSw[pv]);
                    mma16816h(dreg[2 * pv],     pa, vb[0], vb[1]);
                    mma16816h(dreg[2 * pv + 1], pa, vb[2], vb[3]);
                }
            }
            #pragma unroll
            for (int n = 0; n < 8; n++) {
                float2 d0 = __half22float2(*reinterpret_cast<__half2*>(&dreg[n][0]));
                float2 d1 = __half22float2(*reinterpret_cast<__half2*>(&dreg[n][1]));
                o[n][0] = o[n][0] * a0 + d0.x;
                o[n][1] = o[n][1] * a0 + d0.y;
                o[n][2] = o[n][2] * a1 + d1.x;
                o[n][3] = o[n][3] * a1 + d1.y;
            }
        }
        buf = nstage;
    }

    l0 += __shfl_xor_sync(0xffffffffu, l0, 1);
    l0 += __shfl_xor_sync(0xffffffffu, l0, 2);
    l1 += __shfl_xor_sync(0xffffffffu, l1, 1);
    l1 += __shfl_xor_sync(0xffffffffu, l1, 2);

    // normalized fp16 partials (guard: empty range -> l == 0 -> store zeros)
    float inv0 = (l0 > 0.f) ? (1.f / l0) : 0.f;
    float inv1 = (l1 > 0.f) ? (1.f / l1) : 0.f;

    long rbase = (long)b * Tn + qw;
    __half* ob = g_po + ((long)half * Bn * Tn + rbase) * HSn;
    #pragma unroll
    for (int n = 0; n < 8; n++) {
        __half2 v0 = __floats2half2_rn(o[n][0] * inv0, o[n][1] * inv0);
        __half2 v1 = __floats2half2_rn(o[n][2] * inv1, o[n][3] * inv1);
        *(__half2*)(ob + (g    ) * HSn + n * 8 + 2 * t) = v0;
        *(__half2*)(ob + (g + 8) * HSn + n * 8 + 2 * t) = v1;
    }
    if (t == 0) {
        long pr = (long)half * Bn * Tn + rbase;
        g_pm[pr + g]     = m0;  g_pl[pr + g]     = l0;
        g_pm[pr + g + 8] = m1;  g_pl[pr + g + 8] = l1;
    }
}

// ---------------------------------------------------------------------------
// Kernel 3: merge the two split-K partials (normalized fp16) and finalize.
// out = sum_i w_i * o_i_norm, with w_i = l_i * 2^(m_i - ms) / D.
// ---------------------------------------------------------------------------
__global__ __launch_bounds__(256) void merge_kernel(float* __restrict__ out)
{
    int tid = threadIdx.x;
    long r = (long)blockIdx.x * 32 + (tid >> 3);
    int d0 = (tid & 7) * 8;

    float m0 = g_pm[r], l0 = g_pl[r];
    float m1 = g_pm[(long)Bn * Tn + r], l1 = g_pl[(long)Bn * Tn + r];
    float ms = fmaxf(m0, m1);
    float w0 = exp2_approx(m0 - ms) * l0;
    float w1 = exp2_approx(m1 - ms) * l1;
    float inv = 1.f / (w0 + w1);
    w0 *= inv; w1 *= inv;

    long base = r * HSn + d0;
    union { uint4 u; __half2 h[4]; } a, c;
    a.u = *(const uint4*)(g_po + base);
    c.u = *(const uint4*)(g_po + (long)Bn * Tn * HSn + base);

    float4 r0, r1;
    {
        float2 a0 = __half22float2(a.h[0]), c0 = __half22float2(c.h[0]);
        float2 a1 = __half22float2(a.h[1]), c1 = __half22float2(c.h[1]);
        r0.x = a0.x * w0 + c0.x * w1;  r0.y = a0.y * w0 + c0.y * w1;
        r0.z = a1.x * w0 + c1.x * w1;  r0.w = a1.y * w0 + c1.y * w1;
        float2 a2 = __half22float2(a.h[2]), c2 = __half22float2(c.h[2]);
        float2 a3 = __half22float2(a.h[3]), c3 = __half22float2(c.h[3]);
        r1.x = a2.x * w0 + c2.x * w1;  r1.y = a2.y * w0 + c2.y * w1;
        r1.z = a3.x * w0 + c3.x * w1;  r1.w = a3.y * w0 + c3.y * w1;
    }
    float4* po = (float4*)(out + base);
    po[0] = r0;
    po[1] = r1;
}

// ---------------------------------------------------------------------------
extern "C" void kernel_launch(void* const* d_in, const int* in_sizes, int n_in,
                              void* d_out, int out_size) {
    const float* x    = (const float*)d_in[0];
    const float* Wq   = (const float*)d_in[1];
    const float* Wk   = (const float*)d_in[2];
    const float* Wv   = (const float*)d_in[3];
    const float* fcos = (const float*)d_in[4];
    const float* fsin = (const float*)d_in[5];
    const int*   mask = (const int*)d_in[6];
    float* out = (float*)d_out;

    qkv_kernel<<<Bn * Tn / 64, 384>>>(x, Wq, Wk, Wv, fcos, fsin, mask);
    dim3 grid(2 * Tn / BQ, Bn);
    flash_kernel<<<grid, 256>>>();
    merge_kernel<<<Bn * Tn / 32, 256>>>(out);
}